// round 16
// baseline (speedup 1.0000x reference)
#include <cuda_runtime.h>
#include <cuda_bf16.h>
#include <cstdint>

#define NT 128
#define HID 32
#define NB 4

// ---------------- device-global prebuilt parameter buffers ----------------
// B fragments for layers 1,2 in exact mma.m16n8k16 B-fragment order:
// index [l][b][kt][nt][lane] -> uint2 {reg0 (k=kt*16+tid*2+{0,1}), reg1 (+8)}
__device__ uint2  gFragHi[2 * NB * 2 * 4 * 32];
__device__ uint2  gFragLo[2 * NB * 2 * 4 * 32];
__device__ float4 gW04[NB * HID];      // (W0[0][j], W0[1][j], W0[2][j], b0[j])
__device__ float  gBias12[2 * NB * HID];  // b1, b2
__device__ float  gW3v[NB * HID];
__device__ float  gb3v[NB];

// ---------------- helpers ----------------
// Single-MUFU tanh (sm_75+). Measured contribution to rel_err: ~4e-6 (R9).
__device__ __forceinline__ float tanha(float z) {
    float y; asm("tanh.approx.f32 %0, %1;" : "=f"(y) : "f"(z)); return y;
}
// pack two f32 -> bf16x2 word, LOW half = first arg
__device__ __forceinline__ uint32_t cvt2(float lo, float hi) {
    uint32_t d; asm("cvt.rn.bf16x2.f32 %0, %1, %2;" : "=r"(d) : "f"(hi), "f"(lo)); return d;
}
__device__ __forceinline__ void mma_bf16(float* c, const uint32_t* a, uint2 b) {
    asm volatile(
        "mma.sync.aligned.m16n8k16.row.col.f32.bf16.bf16.f32 "
        "{%0,%1,%2,%3}, {%4,%5,%6,%7}, {%8,%9}, {%0,%1,%2,%3};"
        : "+f"(c[0]), "+f"(c[1]), "+f"(c[2]), "+f"(c[3])
        : "r"(a[0]), "r"(a[1]), "r"(a[2]), "r"(a[3]), "r"(b.x), "r"(b.y));
}

// C fragments (2 mtiles x 4 ntiles x 4 f32) -> A fragments hi/lo [mt][kt][4]
// Identity: A(m16k16) of ktile kt = [C_tile(nt=2kt) | C_tile(nt=2kt+1)]
__device__ __forceinline__ void conv_A(const float Cc[2][4][4],
                                       uint32_t Ah[2][2][4], uint32_t Al[2][2][4]) {
#pragma unroll
    for (int mt = 0; mt < 2; mt++)
#pragma unroll
        for (int kt = 0; kt < 2; kt++)
#pragma unroll
            for (int i = 0; i < 2; i++) {
                const float* cf = Cc[mt][2 * kt + i];
                uint32_t h0 = cvt2(cf[0], cf[1]);
                uint32_t h1 = cvt2(cf[2], cf[3]);
                float r00 = cf[0] - __uint_as_float(h0 << 16);
                float r01 = cf[1] - __uint_as_float(h0 & 0xffff0000u);
                float r10 = cf[2] - __uint_as_float(h1 << 16);
                float r11 = cf[3] - __uint_as_float(h1 & 0xffff0000u);
                Ah[mt][kt][2 * i]     = h0;
                Ah[mt][kt][2 * i + 1] = h1;
                Al[mt][kt][2 * i]     = cvt2(r00, r01);
                Al[mt][kt][2 * i + 1] = cvt2(r10, r11);
            }
}

// ---------------- prep kernel: build fragments + params ----------------
__global__ void prep_kernel(
    const float* __restrict__ W0, const float* __restrict__ b0,
    const float* __restrict__ W1, const float* __restrict__ b1,
    const float* __restrict__ W2, const float* __restrict__ b2,
    const float* __restrict__ W3, const float* __restrict__ b3) {
    const int gsz = gridDim.x * blockDim.x;
    int i0 = blockIdx.x * blockDim.x + threadIdx.x;

    // B fragments: 2048 uint2 entries, each holds 2 regs (4 bf16) hi + lo
    for (int f = i0; f < 2 * NB * 2 * 4 * 32; f += gsz) {
        int lane = f & 31;
        int nt = (f >> 5) & 3;
        int kt = (f >> 7) & 1;
        int b  = (f >> 8) & 3;
        int l  = (f >> 10) & 1;
        int g = lane >> 2, tid4 = lane & 3;
        int n = nt * 8 + g;
        const float* src = l ? W2 : W1;
        uint32_t hw[2], lw[2];
#pragma unroll
        for (int r = 0; r < 2; r++) {
            int k0 = kt * 16 + tid4 * 2 + r * 8;
            float v0 = src[b * 1024 + k0 * 32 + n];
            float v1 = src[b * 1024 + (k0 + 1) * 32 + n];
            uint32_t h = cvt2(v0, v1);
            float r0 = v0 - __uint_as_float(h << 16);
            float r1 = v1 - __uint_as_float(h & 0xffff0000u);
            hw[r] = h;
            lw[r] = cvt2(r0, r1);
        }
        gFragHi[f] = make_uint2(hw[0], hw[1]);
        gFragLo[f] = make_uint2(lw[0], lw[1]);
    }
    // layer0 coefficients
    for (int i = i0; i < NB * HID; i += gsz) {
        int b = i >> 5, j = i & 31;
        gW04[i] = make_float4(W0[b * 96 + 0 * 32 + j],
                              W0[b * 96 + 1 * 32 + j],
                              W0[b * 96 + 2 * 32 + j],
                              b0[i]);
        gW3v[i] = W3[i];
    }
    for (int i = i0; i < 2 * NB * HID; i += gsz) {
        int l = i >> 7;
        int r = i & 127;
        gBias12[i] = l ? b2[r] : b1[r];
    }
    if (i0 < NB) gb3v[i0] = b3[i0];
}

// ---------------- main kernel ----------------
__global__ void __launch_bounds__(NT, 4) pfnn_mma(
    const float* __restrict__ x, float* __restrict__ out, int n) {
    __shared__ uint2  sFH[2 * NB * 2 * 4 * 32];
    __shared__ uint2  sFL[2 * NB * 2 * 4 * 32];
    __shared__ float4 sW04[NB * HID];
    __shared__ float  sB12[2 * NB * HID];
    __shared__ float  sW3s[NB * HID];
    __shared__ float  sb3s[NB];

    const int tidx = threadIdx.x;
    for (int i = tidx; i < 2048; i += NT) { sFH[i] = gFragHi[i]; sFL[i] = gFragLo[i]; }
    for (int i = tidx; i < NB * HID; i += NT) { sW04[i] = gW04[i]; sW3s[i] = gW3v[i]; }
    for (int i = tidx; i < 2 * NB * HID; i += NT) sB12[i] = gBias12[i];
    if (tidx < NB) sb3s[tidx] = gb3v[tidx];
    __syncthreads();

    const int wid = tidx >> 5;
    const int lane = tidx & 31;
    const int g = lane >> 2, tid4 = lane & 3;
    const int warpstart = blockIdx.x * NT + wid * 32;

    // this lane's point (for x distribution only)
    int p = warpstart + lane;
    int pc = (p < n) ? p : (n - 1);
    float mx0 = x[3 * pc], mx1 = x[3 * pc + 1], mx2 = x[3 * pc + 2];

    // x of the 4 rows this thread owns: q = mt*2 + h, row = mt*16 + g + 8h
    float rx[4], ry[4], rz[4];
#pragma unroll
    for (int q = 0; q < 4; q++) {
        int src = ((q >> 1) << 4) + g + ((q & 1) << 3);
        rx[q] = __shfl_sync(0xffffffffu, mx0, src);
        ry[q] = __shfl_sync(0xffffffffu, mx1, src);
        rz[q] = __shfl_sync(0xffffffffu, mx2, src);
    }

    float obuf[4] = {0.f, 0.f, 0.f, 0.f};

#pragma unroll 1
    for (int b = 0; b < NB; b++) {
        float Cc[2][4][4];

        // ---- layer 0: 3 -> 32 directly in C-fragment layout ----
#pragma unroll
        for (int nt = 0; nt < 4; nt++) {
            int j0 = nt * 8 + 2 * tid4;
            float4 q0 = sW04[b * HID + j0];
            float4 q1 = sW04[b * HID + j0 + 1];
#pragma unroll
            for (int mt = 0; mt < 2; mt++) {
                float za = fmaf(rx[mt * 2], q0.x, fmaf(ry[mt * 2], q0.y, fmaf(rz[mt * 2], q0.z, q0.w)));
                float zb = fmaf(rx[mt * 2], q1.x, fmaf(ry[mt * 2], q1.y, fmaf(rz[mt * 2], q1.z, q1.w)));
                float zc = fmaf(rx[mt * 2 + 1], q0.x, fmaf(ry[mt * 2 + 1], q0.y, fmaf(rz[mt * 2 + 1], q0.z, q0.w)));
                float zd = fmaf(rx[mt * 2 + 1], q1.x, fmaf(ry[mt * 2 + 1], q1.y, fmaf(rz[mt * 2 + 1], q1.z, q1.w)));
                Cc[mt][nt][0] = tanha(za);
                Cc[mt][nt][1] = tanha(zb);
                Cc[mt][nt][2] = tanha(zc);
                Cc[mt][nt][3] = tanha(zd);
            }
        }

        uint32_t Ah[2][2][4], Al[2][2][4];
        conv_A(Cc, Ah, Al);

        // ---- layers 1,2: tensor-core 32x32 with 3-pass split-bf16 ----
#pragma unroll 1
        for (int l = 0; l < 2; l++) {
            uint2 Bh[2][4], Bl[2][4];
            int fbase = ((l * NB + b) * 2) * 4 * 32;
#pragma unroll
            for (int kt = 0; kt < 2; kt++)
#pragma unroll
                for (int nt = 0; nt < 4; nt++) {
                    int fi = fbase + (kt * 4 + nt) * 32 + lane;
                    Bh[kt][nt] = sFH[fi];
                    Bl[kt][nt] = sFL[fi];
                }
            // init C with bias
#pragma unroll
            for (int nt = 0; nt < 4; nt++) {
                float v0 = sB12[(l * NB + b) * HID + nt * 8 + 2 * tid4];
                float v1 = sB12[(l * NB + b) * HID + nt * 8 + 2 * tid4 + 1];
#pragma unroll
                for (int mt = 0; mt < 2; mt++) {
                    Cc[mt][nt][0] = v0; Cc[mt][nt][1] = v1;
                    Cc[mt][nt][2] = v0; Cc[mt][nt][3] = v1;
                }
            }
            // mma: hi*hi + lo*hi + hi*lo over 2 k-tiles
#pragma unroll
            for (int mt = 0; mt < 2; mt++)
#pragma unroll
                for (int nt = 0; nt < 4; nt++) {
                    mma_bf16(Cc[mt][nt], Ah[mt][0], Bh[0][nt]);
                    mma_bf16(Cc[mt][nt], Ah[mt][1], Bh[1][nt]);
                    mma_bf16(Cc[mt][nt], Al[mt][0], Bh[0][nt]);
                    mma_bf16(Cc[mt][nt], Al[mt][1], Bh[1][nt]);
                    mma_bf16(Cc[mt][nt], Ah[mt][0], Bl[0][nt]);
                    mma_bf16(Cc[mt][nt], Ah[mt][1], Bl[1][nt]);
                }
            // tanh (single MUFU per element)
#pragma unroll
            for (int mt = 0; mt < 2; mt++)
#pragma unroll
                for (int nt = 0; nt < 4; nt++)
#pragma unroll
                    for (int e = 0; e < 4; e++)
                        Cc[mt][nt][e] = tanha(Cc[mt][nt][e]);

            if (l == 0) conv_A(Cc, Ah, Al);
        }

        // ---- layer 3: 32 -> 1, butterfly reduce across the 4-lane group ----
        float s[4] = {0.f, 0.f, 0.f, 0.f};
#pragma unroll
        for (int nt = 0; nt < 4; nt++) {
            float w0 = sW3s[b * HID + nt * 8 + 2 * tid4];
            float w1 = sW3s[b * HID + nt * 8 + 2 * tid4 + 1];
#pragma unroll
            for (int mt = 0; mt < 2; mt++) {
                s[mt * 2 + 0] = fmaf(Cc[mt][nt][0], w0, fmaf(Cc[mt][nt][1], w1, s[mt * 2 + 0]));
                s[mt * 2 + 1] = fmaf(Cc[mt][nt][2], w0, fmaf(Cc[mt][nt][3], w1, s[mt * 2 + 1]));
            }
        }
#pragma unroll
        for (int q = 0; q < 4; q++) {
            s[q] += __shfl_xor_sync(0xffffffffu, s[q], 1);
            s[q] += __shfl_xor_sync(0xffffffffu, s[q], 2);
        }
        if (tid4 == b) {
#pragma unroll
            for (int q = 0; q < 4; q++) obuf[q] = s[q] + sb3s[b];
        }
    }

    // ---- store: lane group (tid4=0..3) writes 4 consecutive branch floats of each row ----
#pragma unroll
    for (int q = 0; q < 4; q++) {
        int row = ((q >> 1) << 4) + g + ((q & 1) << 3);
        int pp = warpstart + row;
        if (pp < n) out[pp * 4 + tid4] = obuf[q];
    }
}

extern "C" void kernel_launch(void* const* d_in, const int* in_sizes, int n_in,
                              void* d_out, int out_size) {
    const float* x  = (const float*)d_in[0];
    const float* W0 = (const float*)d_in[1];
    const float* b0 = (const float*)d_in[2];
    const float* W1 = (const float*)d_in[3];
    const float* b1 = (const float*)d_in[4];
    const float* W2 = (const float*)d_in[5];
    const float* b2 = (const float*)d_in[6];
    const float* W3 = (const float*)d_in[7];
    const float* b3 = (const float*)d_in[8];
    float* out = (float*)d_out;

    const int n = in_sizes[0] / 3;

    prep_kernel<<<8, 256>>>(W0, b0, W1, b1, W2, b2, W3, b3);

    const int blocks = (n + NT - 1) / NT;
    pfnn_mma<<<blocks, NT>>>(x, out, n);
}

// round 17
// speedup vs baseline: 1.1866x; 1.1866x over previous
#include <cuda_runtime.h>
#include <cuda_fp16.h>
#include <cstdint>

#define NT 128
#define HID 32
#define NB 4

// ---------------- device-global prebuilt parameter buffers ----------------
// B fragments (fp16 hi only) for layers 1,2 in exact mma.m16n8k16 B-fragment order:
// index [l][b][kt][nt][lane] -> uint2 {reg0 (k=kt*16+tid*2+{0,1}), reg1 (+8)}
__device__ uint2  gFragHi[2 * NB * 2 * 4 * 32];
__device__ float4 gW04[NB * HID];      // (W0[0][j], W0[1][j], W0[2][j], b0[j])
__device__ float  gBias12[2 * NB * HID];  // b1, b2
__device__ float  gW3v[NB * HID];
__device__ float  gb3v[NB];

// ---------------- helpers ----------------
// Single-MUFU tanh (sm_75+). Measured contribution to rel_err: ~4e-6 (R9).
__device__ __forceinline__ float tanha(float z) {
    float y; asm("tanh.approx.f32 %0, %1;" : "=f"(y) : "f"(z)); return y;
}
// pack two f32 -> f16x2 word, LOW half = first arg
__device__ __forceinline__ uint32_t cvt2h(float lo, float hi) {
    uint32_t d; asm("cvt.rn.f16x2.f32 %0, %1, %2;" : "=r"(d) : "f"(hi), "f"(lo)); return d;
}
__device__ __forceinline__ void mma_f16(float* c, const uint32_t* a, uint2 b) {
    asm volatile(
        "mma.sync.aligned.m16n8k16.row.col.f32.f16.f16.f32 "
        "{%0,%1,%2,%3}, {%4,%5,%6,%7}, {%8,%9}, {%0,%1,%2,%3};"
        : "+f"(c[0]), "+f"(c[1]), "+f"(c[2]), "+f"(c[3])
        : "r"(a[0]), "r"(a[1]), "r"(a[2]), "r"(a[3]), "r"(b.x), "r"(b.y));
}

// C fragments (2 mtiles x 4 ntiles x 4 f32) -> fp16 A fragments hi/lo [mt][kt][4]
// Identity: A(m16k16) of ktile kt = [C_tile(nt=2kt) | C_tile(nt=2kt+1)]
__device__ __forceinline__ void conv_A(const float Cc[2][4][4],
                                       uint32_t Ah[2][2][4], uint32_t Al[2][2][4]) {
#pragma unroll
    for (int mt = 0; mt < 2; mt++)
#pragma unroll
        for (int kt = 0; kt < 2; kt++)
#pragma unroll
            for (int i = 0; i < 2; i++) {
                const float* cf = Cc[mt][2 * kt + i];
                uint32_t h0 = cvt2h(cf[0], cf[1]);
                uint32_t h1 = cvt2h(cf[2], cf[3]);
                float2 f0 = __half22float2(*reinterpret_cast<__half2*>(&h0));
                float2 f1 = __half22float2(*reinterpret_cast<__half2*>(&h1));
                Ah[mt][kt][2 * i]     = h0;
                Ah[mt][kt][2 * i + 1] = h1;
                Al[mt][kt][2 * i]     = cvt2h(cf[0] - f0.x, cf[1] - f0.y);
                Al[mt][kt][2 * i + 1] = cvt2h(cf[2] - f1.x, cf[3] - f1.y);
            }
}

// ---------------- prep kernel: build fp16 B fragments + params ----------------
__global__ void prep_kernel(
    const float* __restrict__ W0, const float* __restrict__ b0,
    const float* __restrict__ W1, const float* __restrict__ b1,
    const float* __restrict__ W2, const float* __restrict__ b2,
    const float* __restrict__ W3, const float* __restrict__ b3) {
    const int gsz = gridDim.x * blockDim.x;
    int i0 = blockIdx.x * blockDim.x + threadIdx.x;

    // B fragments: 2048 uint2 entries (fp16 hi only)
    for (int f = i0; f < 2 * NB * 2 * 4 * 32; f += gsz) {
        int lane = f & 31;
        int nt = (f >> 5) & 3;
        int kt = (f >> 7) & 1;
        int b  = (f >> 8) & 3;
        int l  = (f >> 10) & 1;
        int g = lane >> 2, tid4 = lane & 3;
        int n = nt * 8 + g;
        const float* src = l ? W2 : W1;
        uint32_t hw[2];
#pragma unroll
        for (int r = 0; r < 2; r++) {
            int k0 = kt * 16 + tid4 * 2 + r * 8;
            float v0 = src[b * 1024 + k0 * 32 + n];
            float v1 = src[b * 1024 + (k0 + 1) * 32 + n];
            hw[r] = cvt2h(v0, v1);
        }
        gFragHi[f] = make_uint2(hw[0], hw[1]);
    }
    // layer0 coefficients
    for (int i = i0; i < NB * HID; i += gsz) {
        int b = i >> 5, j = i & 31;
        gW04[i] = make_float4(W0[b * 96 + 0 * 32 + j],
                              W0[b * 96 + 1 * 32 + j],
                              W0[b * 96 + 2 * 32 + j],
                              b0[i]);
        gW3v[i] = W3[i];
    }
    for (int i = i0; i < 2 * NB * HID; i += gsz) {
        int l = i >> 7;
        int r = i & 127;
        gBias12[i] = l ? b2[r] : b1[r];
    }
    if (i0 < NB) gb3v[i0] = b3[i0];
}

// ---------------- main kernel ----------------
__global__ void __launch_bounds__(NT, 4) pfnn_mma(
    const float* __restrict__ x, float* __restrict__ out, int n) {
    __shared__ uint2  sFH[2 * NB * 2 * 4 * 32];
    __shared__ float4 sW04[NB * HID];
    __shared__ float  sB12[2 * NB * HID];
    __shared__ float  sW3s[NB * HID];
    __shared__ float  sb3s[NB];

    const int tidx = threadIdx.x;
    for (int i = tidx; i < 2048; i += NT) sFH[i] = gFragHi[i];
    for (int i = tidx; i < NB * HID; i += NT) { sW04[i] = gW04[i]; sW3s[i] = gW3v[i]; }
    for (int i = tidx; i < 2 * NB * HID; i += NT) sB12[i] = gBias12[i];
    if (tidx < NB) sb3s[tidx] = gb3v[tidx];
    __syncthreads();

    const int wid = tidx >> 5;
    const int lane = tidx & 31;
    const int g = lane >> 2, tid4 = lane & 3;
    const int warpstart = blockIdx.x * NT + wid * 32;

    // this lane's point (for x distribution only)
    int p = warpstart + lane;
    int pc = (p < n) ? p : (n - 1);
    float mx0 = x[3 * pc], mx1 = x[3 * pc + 1], mx2 = x[3 * pc + 2];

    // x of the 4 rows this thread owns: q = mt*2 + h, row = mt*16 + g + 8h
    float rx[4], ry[4], rz[4];
#pragma unroll
    for (int q = 0; q < 4; q++) {
        int src = ((q >> 1) << 4) + g + ((q & 1) << 3);
        rx[q] = __shfl_sync(0xffffffffu, mx0, src);
        ry[q] = __shfl_sync(0xffffffffu, mx1, src);
        rz[q] = __shfl_sync(0xffffffffu, mx2, src);
    }

    float obuf[4] = {0.f, 0.f, 0.f, 0.f};

#pragma unroll 1
    for (int b = 0; b < NB; b++) {
        float Cc[2][4][4];

        // ---- layer 0: 3 -> 32 directly in C-fragment layout ----
#pragma unroll
        for (int nt = 0; nt < 4; nt++) {
            int j0 = nt * 8 + 2 * tid4;
            float4 q0 = sW04[b * HID + j0];
            float4 q1 = sW04[b * HID + j0 + 1];
#pragma unroll
            for (int mt = 0; mt < 2; mt++) {
                float za = fmaf(rx[mt * 2], q0.x, fmaf(ry[mt * 2], q0.y, fmaf(rz[mt * 2], q0.z, q0.w)));
                float zb = fmaf(rx[mt * 2], q1.x, fmaf(ry[mt * 2], q1.y, fmaf(rz[mt * 2], q1.z, q1.w)));
                float zc = fmaf(rx[mt * 2 + 1], q0.x, fmaf(ry[mt * 2 + 1], q0.y, fmaf(rz[mt * 2 + 1], q0.z, q0.w)));
                float zd = fmaf(rx[mt * 2 + 1], q1.x, fmaf(ry[mt * 2 + 1], q1.y, fmaf(rz[mt * 2 + 1], q1.z, q1.w)));
                Cc[mt][nt][0] = tanha(za);
                Cc[mt][nt][1] = tanha(zb);
                Cc[mt][nt][2] = tanha(zc);
                Cc[mt][nt][3] = tanha(zd);
            }
        }

        uint32_t Ah[2][2][4], Al[2][2][4];
        conv_A(Cc, Ah, Al);

        // ---- layers 1,2: tensor-core 32x32, fp16 2-pass split (A refined, B hi) ----
#pragma unroll 1
        for (int l = 0; l < 2; l++) {
            uint2 Bh[2][4];
            int fbase = ((l * NB + b) * 2) * 4 * 32;
#pragma unroll
            for (int kt = 0; kt < 2; kt++)
#pragma unroll
                for (int nt = 0; nt < 4; nt++)
                    Bh[kt][nt] = sFH[fbase + (kt * 4 + nt) * 32 + lane];
            // init C with bias
#pragma unroll
            for (int nt = 0; nt < 4; nt++) {
                float v0 = sB12[(l * NB + b) * HID + nt * 8 + 2 * tid4];
                float v1 = sB12[(l * NB + b) * HID + nt * 8 + 2 * tid4 + 1];
#pragma unroll
                for (int mt = 0; mt < 2; mt++) {
                    Cc[mt][nt][0] = v0; Cc[mt][nt][1] = v1;
                    Cc[mt][nt][2] = v0; Cc[mt][nt][3] = v1;
                }
            }
            // mma: hi*hi + lo*hi over 2 k-tiles (4 MMAs per C tile)
#pragma unroll
            for (int mt = 0; mt < 2; mt++)
#pragma unroll
                for (int nt = 0; nt < 4; nt++) {
                    mma_f16(Cc[mt][nt], Ah[mt][0], Bh[0][nt]);
                    mma_f16(Cc[mt][nt], Ah[mt][1], Bh[1][nt]);
                    mma_f16(Cc[mt][nt], Al[mt][0], Bh[0][nt]);
                    mma_f16(Cc[mt][nt], Al[mt][1], Bh[1][nt]);
                }
            // tanh (single MUFU per element)
#pragma unroll
            for (int mt = 0; mt < 2; mt++)
#pragma unroll
                for (int nt = 0; nt < 4; nt++)
#pragma unroll
                    for (int e = 0; e < 4; e++)
                        Cc[mt][nt][e] = tanha(Cc[mt][nt][e]);

            if (l == 0) conv_A(Cc, Ah, Al);
        }

        // ---- layer 3: 32 -> 1, butterfly reduce across the 4-lane group ----
        float s[4] = {0.f, 0.f, 0.f, 0.f};
#pragma unroll
        for (int nt = 0; nt < 4; nt++) {
            float w0 = sW3s[b * HID + nt * 8 + 2 * tid4];
            float w1 = sW3s[b * HID + nt * 8 + 2 * tid4 + 1];
#pragma unroll
            for (int mt = 0; mt < 2; mt++) {
                s[mt * 2 + 0] = fmaf(Cc[mt][nt][0], w0, fmaf(Cc[mt][nt][1], w1, s[mt * 2 + 0]));
                s[mt * 2 + 1] = fmaf(Cc[mt][nt][2], w0, fmaf(Cc[mt][nt][3], w1, s[mt * 2 + 1]));
            }
        }
#pragma unroll
        for (int q = 0; q < 4; q++) {
            s[q] += __shfl_xor_sync(0xffffffffu, s[q], 1);
            s[q] += __shfl_xor_sync(0xffffffffu, s[q], 2);
        }
        if (tid4 == b) {
#pragma unroll
            for (int q = 0; q < 4; q++) obuf[q] = s[q] + sb3s[b];
        }
    }

    // ---- store: lane group (tid4=0..3) writes 4 consecutive branch floats of each row ----
#pragma unroll
    for (int q = 0; q < 4; q++) {
        int row = ((q >> 1) << 4) + g + ((q & 1) << 3);
        int pp = warpstart + row;
        if (pp < n) out[pp * 4 + tid4] = obuf[q];
    }
}

extern "C" void kernel_launch(void* const* d_in, const int* in_sizes, int n_in,
                              void* d_out, int out_size) {
    const float* x  = (const float*)d_in[0];
    const float* W0 = (const float*)d_in[1];
    const float* b0 = (const float*)d_in[2];
    const float* W1 = (const float*)d_in[3];
    const float* b1 = (const float*)d_in[4];
    const float* W2 = (const float*)d_in[5];
    const float* b2 = (const float*)d_in[6];
    const float* W3 = (const float*)d_in[7];
    const float* b3 = (const float*)d_in[8];
    float* out = (float*)d_out;

    const int n = in_sizes[0] / 3;

    prep_kernel<<<8, 256>>>(W0, b0, W1, b1, W2, b2, W3, b3);

    const int blocks = (n + NT - 1) / NT;
    pfnn_mma<<<blocks, NT>>>(x, out, n);
}